// round 11
// baseline (speedup 1.0000x reference)
#include <cuda_runtime.h>
#include <cuda_bf16.h>

// CasamentoMult on GB300 — lean pipe split: gy/gd/s on MUFU ex2 (3/elt),
// c1/c2 on an fma-pipe polynomial fed directly by the packed squares.
// Values prescaled by SC = sqrt(pi*log2 e), so square v = (SC*diff)^2 gives
//   exp(-pi*diff^2) = 2^(-v):  MUFU path ex2(-v), poly path magic-round 2^-v.
//  total = NE + sum_k [ 0.5*(gy+gd-c1-c2) - s ]
//             + 0.5*e(d[0]-y[0]) - 0.5*e(d[NE]-y[NE]),   NE = N-2.

#define NBLK 1184          // 148 SMs * 8
#define NTHR 256

__device__ float    g_partials[NBLK];
__device__ unsigned g_ticket = 0;

#define SC     2.1289340388624523f   // sqrt(pi * log2(e))
#define MAGICF 12582912.0f           // 1.5*2^23 (0x4B400000, low 9 bits 0)
#define RMIN   0x4B3FFF82            // as_int(MAGICF) - 126

// ---- f32x2 helpers (double containers; FP64 pipe never used) ----
__device__ __forceinline__ double pk2(float lo, float hi) {
    double r; asm("mov.b64 %0, {%1, %2};" : "=d"(r) : "f"(lo), "f"(hi)); return r;
}
__device__ __forceinline__ float lo2(double v) {
    return __uint_as_float((unsigned)__double2loint(v));
}
__device__ __forceinline__ float hi2(double v) {
    return __uint_as_float((unsigned)__double2hiint(v));
}
__device__ __forceinline__ double sub2(double a, double b) {   // a - b
    double r; asm("sub.rn.f32x2 %0, %1, %2;" : "=d"(r) : "d"(a), "d"(b)); return r;
}
__device__ __forceinline__ double mul2(double a, double b) {
    double r; asm("mul.rn.f32x2 %0, %1, %2;" : "=d"(r) : "d"(a), "d"(b)); return r;
}
__device__ __forceinline__ double fma2(double a, double b, double c) {
    double r; asm("fma.rn.f32x2 %0, %1, %2, %3;" : "=d"(r) : "d"(a), "d"(b), "d"(c)); return r;
}
__device__ __forceinline__ float ex2f(float a) {
    float r; asm("ex2.approx.f32 %0, %1;" : "=f"(r) : "f"(a)); return r;
}
__device__ __forceinline__ float gex_raw(float x) {   // exp(-pi*x^2), scalar
    float u = x * SC;
    return ex2f(-(u * u));
}

__global__ void __launch_bounds__(NTHR)
casa_fused(const float* __restrict__ d, const float* __restrict__ y,
           int NE, int ngroups, float* __restrict__ out) {
    const double SC2  = pk2(SC, SC);
    const double NEG1 = pk2(-1.f, -1.f);
    const double MG2  = pk2(MAGICF, MAGICF);
    const double K4   = pk2(0.0096181291f, 0.0096181291f);
    const double K3   = pk2(0.0555041087f, 0.0555041087f);
    const double K2   = pk2(0.2402265069f, 0.2402265069f);
    const double K1   = pk2(0.6931471806f, 0.6931471806f);
    const double K0   = pk2(1.0f, 1.0f);

    float accA0 = 0.f, accA1 = 0.f;   // gy+gd       (+0.5)
    float accS0 = 0.f, accS1 = 0.f;   // s           (-1)
    float accC0 = 0.f, accC1 = 0.f;   // c1+c2 poly  (-0.5)
    const int stride = gridDim.x * blockDim.x;

    for (int g = blockIdx.x * blockDim.x + threadIdx.x; g < ngroups; g += stride) {
        const int base = g << 3;                   // 8 elements per group
        const float4 dA = *reinterpret_cast<const float4*>(d + base);
        const float4 dB = *reinterpret_cast<const float4*>(d + base + 4);
        const float4 yA = *reinterpret_cast<const float4*>(y + base);
        const float4 yB = *reinterpret_cast<const float4*>(y + base + 4);
        const float d8 = __ldg(d + base + 8) * SC;
        const float y8 = __ldg(y + base + 8) * SC;

        // even pairs (k, k+1), prescaled packed
        double Dp[4], Yp[4];
        Dp[0] = mul2(pk2(dA.x, dA.y), SC2);
        Dp[1] = mul2(pk2(dA.z, dA.w), SC2);
        Dp[2] = mul2(pk2(dB.x, dB.y), SC2);
        Dp[3] = mul2(pk2(dB.z, dB.w), SC2);
        Yp[0] = mul2(pk2(yA.x, yA.y), SC2);
        Yp[1] = mul2(pk2(yA.z, yA.w), SC2);
        Yp[2] = mul2(pk2(yB.x, yB.y), SC2);
        Yp[3] = mul2(pk2(yB.z, yB.w), SC2);

        #pragma unroll
        for (int p = 0; p < 4; p++) {
            const float dn = (p < 3) ? lo2(Dp[p + 1]) : d8;
            const float yn = (p < 3) ? lo2(Yp[p + 1]) : y8;
            const double Dq = pk2(hi2(Dp[p]), dn); // (D_{k+1}, D_{k+2})
            const double Yq = pk2(hi2(Yp[p]), yn);

            // ---- MUFU categories: gy, gd, s ----
            const double qG = sub2(Yq, Yp[p]);
            const double qD = sub2(Dq, Dp[p]);
            const double qS = sub2(Dp[p], Yp[p]);
            const double vG = mul2(qG, qG);
            const double vD = mul2(qD, qD);
            const double vS = mul2(qS, qS);
            accA0 += ex2f(-lo2(vG)) + ex2f(-lo2(vD));
            accA1 += ex2f(-hi2(vG)) + ex2f(-hi2(vD));
            accS0 += ex2f(-lo2(vS));
            accS1 += ex2f(-hi2(vS));

            // ---- poly categories: c1, c2 (2^-v via magic round) ----
            #pragma unroll
            for (int c = 0; c < 2; c++) {
                const double q = (c == 0) ? sub2(Dq, Yp[p])   // c1 pair
                                          : sub2(Dp[p], Yq);  // c2 pair
                const double v  = mul2(q, q);           // = pi*log2e*diff^2
                const double r  = fma2(v, NEG1, MG2);   // MAGIC - v
                const double rv = fma2(r, NEG1, MG2);   // round(v)
                const double f  = fma2(v, NEG1, rv);    // round(v)-v in [-.5,.5]
                double pl = fma2(f, K4, K3);
                pl = fma2(pl, f, K2);
                pl = fma2(pl, f, K1);
                pl = fma2(pl, f, K0);                   // 2^f
                int r0 = __double2loint(r), r1 = __double2hiint(r);
                int p0 = __double2loint(pl), p1 = __double2hiint(pl);
                r0 = max(r0, (int)RMIN);                // clamp: v>126 -> ~0
                r1 = max(r1, (int)RMIN);
                // bits = bits(2^f) + (r<<23); MAGICBITS<<23 == 0 mod 2^32
                accC0 += __uint_as_float(((unsigned)r0 << 23) + (unsigned)p0);
                accC1 += __uint_as_float(((unsigned)r1 << 23) + (unsigned)p1);
            }
        }
    }

    // total = 0.5*(A - C) - S
    float acc = fmaf((accA0 + accA1) - (accC0 + accC1), 0.5f,
                     -(accS0 + accS1));

    // block reduce (float)
    #pragma unroll
    for (int o = 16; o; o >>= 1) acc += __shfl_down_sync(0xffffffffu, acc, o);

    __shared__ float sh[NTHR / 32];
    __shared__ bool  s_last;
    const int lane = threadIdx.x & 31;
    const int w    = threadIdx.x >> 5;
    if (lane == 0) sh[w] = acc;
    __syncthreads();
    if (threadIdx.x == 0) {
        float v = 0.f;
        #pragma unroll
        for (int i = 0; i < NTHR / 32; i++) v += sh[i];
        g_partials[blockIdx.x] = v;
        __threadfence();
        unsigned t = atomicAdd(&g_ticket, 1u);
        s_last = (t == (unsigned)gridDim.x - 1u);
    }
    __syncthreads();
    if (!s_last) return;

    // ---- last block: deterministic double-precision finish ----
    const int tid = threadIdx.x;
    double v = 0.0;
    for (int i = tid; i < NBLK; i += NTHR)       // fixed-order per thread
        v += (double)g_partials[i];

    if (tid == 0) {
        for (int k = 8 * ngroups; k < NE; k++) { // tail (empty when NE%8==0)
            float t0 = d[k], t1 = d[k + 1], u0 = y[k], u1 = y[k + 1];
            float a = gex_raw(u1 - u0) + gex_raw(t1 - t0)
                    - gex_raw(t1 - u0) - gex_raw(t0 - u1);
            v += 0.5 * (double)a - (double)gex_raw(t0 - u0);
        }
        v += 0.5 * ((double)gex_raw(d[0] - y[0]) - (double)gex_raw(d[NE] - y[NE]));
        v += (double)NE;
    }

    #pragma unroll
    for (int o = 16; o; o >>= 1) v += __shfl_down_sync(0xffffffffu, v, o);

    __shared__ double shd[NTHR / 32];
    if (lane == 0) shd[w] = v;
    __syncthreads();
    if (tid == 0) {
        double t = 0.0;
        #pragma unroll
        for (int i = 0; i < NTHR / 32; i++) t += shd[i];
        out[0] = (float)t;
        g_ticket = 0;                  // reset for next graph replay
    }
}

extern "C" void kernel_launch(void* const* d_in, const int* in_sizes, int n_in,
                              void* d_out, int out_size) {
    const float* d = (const float*)d_in[0];
    const float* y = (const float*)d_in[1];
    float* out = (float*)d_out;

    const int n  = in_sizes[0];
    const int NE = n - 2;               // 4,000,000 for N = 4,000,002
    const int ngroups = NE / 8;         // 8 consecutive k per group

    casa_fused<<<NBLK, NTHR>>>(d, y, NE, ngroups, out);
}

// round 12
// speedup vs baseline: 1.0043x; 1.0043x over previous
#include <cuda_runtime.h>
#include <cuda_bf16.h>

// CasamentoMult on GB300 — 4 MUFU exps/elt + 1 poly exp/elt, pair-packed.
// Front end = R8 pair packing (rel_err 0), poly tail = R11 magic-round 2^-v
// (rel_err 6.9e-7), applied to category c2 only.
// Prescale by SC = sqrt(pi*log2 e):  exp(-pi*diff^2) = 2^(-v), v=(SC*diff)^2.
//  total = NE + sum_k [ 0.5*(gy+gd-c1-c2) - s ]
//             + 0.5*e(d[0]-y[0]) - 0.5*e(d[NE]-y[NE]),   NE = N-2.

#define NBLK 1184          // 148 SMs * 8
#define NTHR 256

__device__ float    g_partials[NBLK];
__device__ unsigned g_ticket = 0;

#define SC     2.1289340388624523f   // sqrt(pi * log2(e))
#define MAGICF 12582912.0f           // 1.5*2^23 (0x4B400000, low 9 bits 0)
#define RMIN   0x4B3FFF82            // as_int(MAGICF) - 126

// ---- f32x2 helpers (double containers; FP64 pipe never used) ----
__device__ __forceinline__ double pk2(float lo, float hi) {
    double r; asm("mov.b64 %0, {%1, %2};" : "=d"(r) : "f"(lo), "f"(hi)); return r;
}
__device__ __forceinline__ float lo2(double v) {
    return __uint_as_float((unsigned)__double2loint(v));
}
__device__ __forceinline__ float hi2(double v) {
    return __uint_as_float((unsigned)__double2hiint(v));
}
__device__ __forceinline__ double sub2(double a, double b) {   // a - b
    double r; asm("sub.rn.f32x2 %0, %1, %2;" : "=d"(r) : "d"(a), "d"(b)); return r;
}
__device__ __forceinline__ double mul2(double a, double b) {
    double r; asm("mul.rn.f32x2 %0, %1, %2;" : "=d"(r) : "d"(a), "d"(b)); return r;
}
__device__ __forceinline__ double fma2(double a, double b, double c) {
    double r; asm("fma.rn.f32x2 %0, %1, %2, %3;" : "=d"(r) : "d"(a), "d"(b), "d"(c)); return r;
}
__device__ __forceinline__ float ex2f(float a) {
    float r; asm("ex2.approx.f32 %0, %1;" : "=f"(r) : "f"(a)); return r;
}
__device__ __forceinline__ float gex_raw(float x) {   // exp(-pi*x^2), scalar
    float u = x * SC;
    return ex2f(-(u * u));
}

__global__ void __launch_bounds__(NTHR)
casa_fused(const float* __restrict__ d, const float* __restrict__ y,
           int NE, int ngroups, float* __restrict__ out) {
    const double SC2  = pk2(SC, SC);
    const double NEG1 = pk2(-1.f, -1.f);
    const double MG2  = pk2(MAGICF, MAGICF);
    const double K4   = pk2(0.0096181291f, 0.0096181291f);
    const double K3   = pk2(0.0555041087f, 0.0555041087f);
    const double K2   = pk2(0.2402265069f, 0.2402265069f);
    const double K1   = pk2(0.6931471806f, 0.6931471806f);
    const double K0   = pk2(1.0f, 1.0f);

    float accA0 = 0.f, accA1 = 0.f;   // gy+gd        (+0.5)
    float accC0 = 0.f, accC1 = 0.f;   // c1 (MUFU)    (-0.5)
    float accS0 = 0.f, accS1 = 0.f;   // s            (-1)
    float accP0 = 0.f, accP1 = 0.f;   // c2 (poly)    (-0.5)
    const int stride = gridDim.x * blockDim.x;

    for (int g = blockIdx.x * blockDim.x + threadIdx.x; g < ngroups; g += stride) {
        const int base = g << 3;                   // 8 elements per group
        const float4 dA = *reinterpret_cast<const float4*>(d + base);
        const float4 dB = *reinterpret_cast<const float4*>(d + base + 4);
        const float4 yA = *reinterpret_cast<const float4*>(y + base);
        const float4 yB = *reinterpret_cast<const float4*>(y + base + 4);
        const float d8 = __ldg(d + base + 8) * SC;
        const float y8 = __ldg(y + base + 8) * SC;

        // even pairs (k, k+1), prescaled packed (natural register pairs)
        double Dp[4], Yp[4];
        Dp[0] = mul2(pk2(dA.x, dA.y), SC2);
        Dp[1] = mul2(pk2(dA.z, dA.w), SC2);
        Dp[2] = mul2(pk2(dB.x, dB.y), SC2);
        Dp[3] = mul2(pk2(dB.z, dB.w), SC2);
        Yp[0] = mul2(pk2(yA.x, yA.y), SC2);
        Yp[1] = mul2(pk2(yA.z, yA.w), SC2);
        Yp[2] = mul2(pk2(yB.x, yB.y), SC2);
        Yp[3] = mul2(pk2(yB.z, yB.w), SC2);

        #pragma unroll
        for (int p = 0; p < 4; p++) {
            const float dn = (p < 3) ? lo2(Dp[p + 1]) : d8;
            const float yn = (p < 3) ? lo2(Yp[p + 1]) : y8;
            const double Dq = pk2(hi2(Dp[p]), dn); // (D_{k+1}, D_{k+2})
            const double Yq = pk2(hi2(Yp[p]), yn);

            // ---- 4 MUFU categories: gy, gd, s, c1 (two elements each) ----
            const double qG = sub2(Yq, Yp[p]);
            const double qD = sub2(Dq, Dp[p]);
            const double qS = sub2(Dp[p], Yp[p]);
            const double q1 = sub2(Dq, Yp[p]);
            const double vG = mul2(qG, qG);
            const double vD = mul2(qD, qD);
            const double vS = mul2(qS, qS);
            const double v1 = mul2(q1, q1);
            accA0 += ex2f(-lo2(vG)) + ex2f(-lo2(vD));
            accA1 += ex2f(-hi2(vG)) + ex2f(-hi2(vD));
            accC0 += ex2f(-lo2(v1));
            accC1 += ex2f(-hi2(v1));
            accS0 += ex2f(-lo2(vS));
            accS1 += ex2f(-hi2(vS));

            // ---- c2 on fma-pipe poly: 2^-v via magic round (two elements) ----
            const double q2 = sub2(Dp[p], Yq);
            const double v  = mul2(q2, q2);
            const double r  = fma2(v, NEG1, MG2);   // MAGIC - v
            const double rv = fma2(r, NEG1, MG2);   // round(v)
            const double f  = fma2(v, NEG1, rv);    // round(v)-v in [-.5,.5]
            double pl = fma2(f, K4, K3);
            pl = fma2(pl, f, K2);
            pl = fma2(pl, f, K1);
            pl = fma2(pl, f, K0);                   // 2^f
            int r0 = __double2loint(r), r1 = __double2hiint(r);
            int p0 = __double2loint(pl), p1 = __double2hiint(pl);
            r0 = max(r0, (int)RMIN);                // clamp: v>126 -> ~0
            r1 = max(r1, (int)RMIN);
            accP0 += __uint_as_float(((unsigned)r0 << 23) + (unsigned)p0);
            accP1 += __uint_as_float(((unsigned)r1 << 23) + (unsigned)p1);
        }
    }

    // total = 0.5*(A - C1 - C2) - S
    float acc = fmaf((accA0 + accA1) - ((accC0 + accC1) + (accP0 + accP1)),
                     0.5f, -(accS0 + accS1));

    // block reduce (float)
    #pragma unroll
    for (int o = 16; o; o >>= 1) acc += __shfl_down_sync(0xffffffffu, acc, o);

    __shared__ float sh[NTHR / 32];
    __shared__ bool  s_last;
    const int lane = threadIdx.x & 31;
    const int w    = threadIdx.x >> 5;
    if (lane == 0) sh[w] = acc;
    __syncthreads();
    if (threadIdx.x == 0) {
        float v = 0.f;
        #pragma unroll
        for (int i = 0; i < NTHR / 32; i++) v += sh[i];
        g_partials[blockIdx.x] = v;
        __threadfence();
        unsigned t = atomicAdd(&g_ticket, 1u);
        s_last = (t == (unsigned)gridDim.x - 1u);
    }
    __syncthreads();
    if (!s_last) return;

    // ---- last block: deterministic double-precision finish ----
    const int tid = threadIdx.x;
    double v = 0.0;
    for (int i = tid; i < NBLK; i += NTHR)       // fixed-order per thread
        v += (double)g_partials[i];

    if (tid == 0) {
        for (int k = 8 * ngroups; k < NE; k++) { // tail (empty when NE%8==0)
            float t0 = d[k], t1 = d[k + 1], u0 = y[k], u1 = y[k + 1];
            float a = gex_raw(u1 - u0) + gex_raw(t1 - t0)
                    - gex_raw(t1 - u0) - gex_raw(t0 - u1);
            v += 0.5 * (double)a - (double)gex_raw(t0 - u0);
        }
        v += 0.5 * ((double)gex_raw(d[0] - y[0]) - (double)gex_raw(d[NE] - y[NE]));
        v += (double)NE;
    }

    #pragma unroll
    for (int o = 16; o; o >>= 1) v += __shfl_down_sync(0xffffffffu, v, o);

    __shared__ double shd[NTHR / 32];
    if (lane == 0) shd[w] = v;
    __syncthreads();
    if (tid == 0) {
        double t = 0.0;
        #pragma unroll
        for (int i = 0; i < NTHR / 32; i++) t += shd[i];
        out[0] = (float)t;
        g_ticket = 0;                  // reset for next graph replay
    }
}

extern "C" void kernel_launch(void* const* d_in, const int* in_sizes, int n_in,
                              void* d_out, int out_size) {
    const float* d = (const float*)d_in[0];
    const float* y = (const float*)d_in[1];
    float* out = (float*)d_out;

    const int n  = in_sizes[0];
    const int NE = n - 2;               // 4,000,000 for N = 4,000,002
    const int ngroups = NE / 8;         // 8 consecutive k per group

    casa_fused<<<NBLK, NTHR>>>(d, y, NE, ngroups, out);
}